// round 10
// baseline (speedup 1.0000x reference)
#include <cuda_runtime.h>
#include <cuda_bf16.h>
#include <cstdint>
#include <cstddef>

#define F 128
#define NPMAX 50000
#define NAMAX 100000
#define EMAX 800000
#define N3MAX (2 * NPMAX + NAMAX)

// ============================ helpers ============================
__device__ __forceinline__ uint32_t smem_u32(const void* p) {
    uint32_t a;
    asm("{ .reg .u64 t; cvta.to.shared.u64 t, %1; cvt.u32.u64 %0, t; }" : "=r"(a) : "l"(p));
    return a;
}
__device__ __forceinline__ void ldm_x4(uint32_t* r, uint32_t addr) {
    asm volatile("ldmatrix.sync.aligned.m8n8.x4.shared.b16 {%0,%1,%2,%3}, [%4];"
                 : "=r"(r[0]), "=r"(r[1]), "=r"(r[2]), "=r"(r[3]) : "r"(addr));
}
__device__ __forceinline__ void mma_bf16(float* c, const uint32_t* a, const uint32_t* b) {
    asm volatile(
        "mma.sync.aligned.m16n8k16.row.col.f32.bf16.bf16.f32 "
        "{%0,%1,%2,%3}, {%4,%5,%6,%7}, {%8,%9}, {%0,%1,%2,%3};"
        : "+f"(c[0]), "+f"(c[1]), "+f"(c[2]), "+f"(c[3])
        : "r"(a[0]), "r"(a[1]), "r"(a[2]), "r"(a[3]), "r"(b[0]), "r"(b[1]));
}

// [rows x 128 bf16] tile, 256B/row, 16B chunks, XOR swizzle chunk^(row&7)
__device__ __forceinline__ uint32_t tile_off(int row, int ch) {
    return (uint32_t)(row * 256 + ((ch ^ (row & 7)) << 4));
}

// ============================ device scratch ============================
__device__ float g_agg_c[(size_t)NPMAX * F];
__device__ float g_agg_a[(size_t)NPMAX * F];
__device__ float g_agg_h[(size_t)NAMAX * F];
__device__ float g_agg_c2[(size_t)NPMAX * F];
__device__ float g_agg_a2[(size_t)NPMAX * F];
__device__ float g_p1[(size_t)NPMAX * F];
__device__ float g_a1[(size_t)NAMAX * F];
__device__ float g_pbuf[(size_t)NPMAX * F];     // agg_a2@Wl6 + p1@Wr2 partial (raw)
__device__ float g_b1[F];
__device__ float g_b2[F];
__device__ __nv_bfloat16 g_wblob[8][2][F * F];  // [matrix][hi/lo][tile-image layout]
// fused CSR over 3 relations: segments [0,NP) c | [NP,2NP) a | [2NP,2NP+NA) h
__device__ int g_cnt3[N3MAX];
__device__ int g_rp3[N3MAX + 1];
__device__ int g_col3[3 * EMAX];
__device__ int g_part[128];

// ============================ fused CSR build ============================
__global__ void count3_kernel(const int* __restrict__ cd, const int* __restrict__ ad,
                              const int* __restrict__ hd, int* __restrict__ cnt3,
                              int E, int NP) {
    int i = blockIdx.x * blockDim.x + threadIdx.x;
    if (i < E) atomicAdd(&cnt3[cd[i]], 1);
    else if (i < 2 * E) atomicAdd(&cnt3[NP + ad[i - E]], 1);
    else if (i < 3 * E) atomicAdd(&cnt3[2 * NP + hd[i - 2 * E]], 1);
}

__global__ void __launch_bounds__(1024) scanA_kernel(const int* __restrict__ cnt,
                                                     int* __restrict__ part, int n) {
    __shared__ int wsum[32];
    int tid = threadIdx.x;
    int base = blockIdx.x * 2048 + tid * 2;
    int v = 0;
    if (base < n) v += cnt[base];
    if (base + 1 < n) v += cnt[base + 1];
#pragma unroll
    for (int o = 16; o; o >>= 1) v += __shfl_down_sync(0xFFFFFFFF, v, o);
    if ((tid & 31) == 0) wsum[tid >> 5] = v;
    __syncthreads();
    if (tid < 32) {
        int x = wsum[tid];
#pragma unroll
        for (int o = 16; o; o >>= 1) x += __shfl_down_sync(0xFFFFFFFF, x, o);
        if (tid == 0) part[blockIdx.x] = x;
    }
}

__global__ void scanB_kernel(int* __restrict__ part, int* __restrict__ rp_end, int nb) {
    __shared__ int ws[4];
    int tid = threadIdx.x;     // 128 threads
    int lane = tid & 31, w = tid >> 5;
    int v = (tid < nb) ? part[tid] : 0;
    int x = v;
#pragma unroll
    for (int o = 1; o < 32; o <<= 1) {
        int y = __shfl_up_sync(0xFFFFFFFF, x, o);
        if (lane >= o) x += y;
    }
    if (lane == 31) ws[w] = x;
    __syncthreads();
    int add = 0;
#pragma unroll
    for (int i = 0; i < 4; i++) add += (i < w) ? ws[i] : 0;
    x += add;
    if (tid < nb) part[tid] = x - v;   // exclusive block offset
    if (tid == 127) *rp_end = x;       // grand total
}

__global__ void __launch_bounds__(1024) scanC_kernel(const int* __restrict__ cnt,
                                                     const int* __restrict__ part,
                                                     int* __restrict__ rp, int n) {
    __shared__ int woff[32];
    int tid = threadIdx.x;
    int lane = tid & 31, w = tid >> 5;
    int base = blockIdx.x * 2048 + tid * 2;
    int e0 = (base < n) ? cnt[base] : 0;
    int e1 = (base + 1 < n) ? cnt[base + 1] : 0;
    int p = e0 + e1;
    int x = p;
#pragma unroll
    for (int o = 1; o < 32; o <<= 1) {
        int y = __shfl_up_sync(0xFFFFFFFF, x, o);
        if (lane >= o) x += y;
    }
    if (lane == 31) woff[w] = x;
    __syncthreads();
    if (tid < 32) {
        int y = woff[tid];
        int z = y;
#pragma unroll
        for (int o = 1; o < 32; o <<= 1) {
            int t = __shfl_up_sync(0xFFFFFFFF, z, o);
            if (tid >= o) z += t;
        }
        woff[tid] = z - y;
    }
    __syncthreads();
    int off = part[blockIdx.x] + woff[w] + x - p;
    if (base < n) rp[base] = off;
    if (base + 1 < n) rp[base + 1] = off + e0;
}

// uses cnt3 as a countdown cursor (fill order within a segment reversed: irrelevant for sums)
__global__ void fill3_kernel(const int* __restrict__ cs, const int* __restrict__ cd,
                             const int* __restrict__ as, const int* __restrict__ ad,
                             const int* __restrict__ hs, const int* __restrict__ hd,
                             const int* __restrict__ rp3, int* __restrict__ cnt3,
                             int* __restrict__ col3, int E, int NP) {
    int i = blockIdx.x * blockDim.x + threadIdx.x;
    int s, d;
    if (i < E) { s = cs[i]; d = cd[i]; }
    else if (i < 2 * E) { s = as[i - E]; d = NP + ad[i - E]; }
    else if (i < 3 * E) { s = hs[i - 2 * E]; d = 2 * NP + hd[i - 2 * E]; }
    else return;
    int p = atomicSub(&cnt3[d], 1) - 1;
    col3[rp3[d] + p] = s;
}

// ============================ CSR mean-gather: warp per dst node, unroll-2 ============================
__global__ void __launch_bounds__(256) gather_kernel(const float* __restrict__ x,
                                                     const int* __restrict__ rp,
                                                     const int* __restrict__ col,
                                                     float* __restrict__ out, int n) {
    int w = (blockIdx.x * blockDim.x + threadIdx.x) >> 5;
    int lane = threadIdx.x & 31;
    if (w >= n) return;
    int s = __ldg(&rp[w]);
    int e = __ldg(&rp[w + 1]);
    float4 acc0 = make_float4(0.f, 0.f, 0.f, 0.f);
    float4 acc1 = make_float4(0.f, 0.f, 0.f, 0.f);
    int i = s;
    for (; i + 2 <= e; i += 2) {
        int c0 = __ldg(&col[i]);
        int c1 = __ldg(&col[i + 1]);
        float4 v0 = *(const float4*)(x + (size_t)c0 * F + lane * 4);
        float4 v1 = *(const float4*)(x + (size_t)c1 * F + lane * 4);
        acc0.x += v0.x; acc0.y += v0.y; acc0.z += v0.z; acc0.w += v0.w;
        acc1.x += v1.x; acc1.y += v1.y; acc1.z += v1.z; acc1.w += v1.w;
    }
    if (i < e) {
        int c = __ldg(&col[i]);
        float4 v = *(const float4*)(x + (size_t)c * F + lane * 4);
        acc0.x += v.x; acc0.y += v.y; acc0.z += v.z; acc0.w += v.w;
    }
    float sc = 1.0f / fmaxf((float)(e - s), 1.0f);
    *(float4*)(out + (size_t)w * F + lane * 4) =
        make_float4((acc0.x + acc1.x) * sc, (acc0.y + acc1.y) * sc,
                    (acc0.z + acc1.z) * sc, (acc0.w + acc1.w) * sc);
}

// ============================ small kernels ============================
__global__ void prep_bias_kernel(const float* __restrict__ b1c, const float* __restrict__ b1a,
                                 const float* __restrict__ b2c, const float* __restrict__ b2a) {
    int i = threadIdx.x;
    if (i < F) {
        g_b1[i] = 0.5f * (b1c[i] + b1a[i]);
        g_b2[i] = 0.5f * (b2c[i] + b2a[i]);
    }
}

struct W8 { const float* a[8]; const float* b[8]; };

__global__ void prep_w_kernel(W8 w) {
    int mat = blockIdx.y;
    int ci = blockIdx.x * 256 + threadIdx.x;   // 0..2047, chunk of 8 elems
    if (ci >= 2048) return;
    int row = ci >> 4, ch = ci & 15;
    const float* pa = w.a[mat];
    const float* pb = w.b[mat];
    int base = row * F + ch * 8;
    uint32_t hi[4], lo[4];
#pragma unroll
    for (int j = 0; j < 4; j++) {
        float x0 = pa[base + 2 * j], x1 = pa[base + 2 * j + 1];
        if (pb) { x0 += pb[base + 2 * j]; x1 += pb[base + 2 * j + 1]; }
        __nv_bfloat16 h0 = __float2bfloat16_rn(x0);
        __nv_bfloat16 h1 = __float2bfloat16_rn(x1);
        __nv_bfloat16 l0 = __float2bfloat16_rn(x0 - __bfloat162float(h0));
        __nv_bfloat16 l1 = __float2bfloat16_rn(x1 - __bfloat162float(h1));
        hi[j] = ((uint32_t)__bfloat16_as_ushort(h1) << 16) | __bfloat16_as_ushort(h0);
        lo[j] = ((uint32_t)__bfloat16_as_ushort(l1) << 16) | __bfloat16_as_ushort(l0);
    }
    uint32_t o = tile_off(row, ch);
    *(uint4*)((char*)&g_wblob[mat][0][0] + o) = make_uint4(hi[0], hi[1], hi[2], hi[3]);
    *(uint4*)((char*)&g_wblob[mat][1][0] + o) = make_uint4(lo[0], lo[1], lo[2], lo[3]);
}

// ============================ mma.sync fused multi-source GEMM (M-tile 64) ============================
// MODE 0: C = relu(alpha*acc + bias)
// MODE 1: C = acc (raw partial)
// MODE 2: head-fused: o = relu(alpha*(acc + pinit) + bias); out = o @ linW^T + linb. No C store.
// MODE 3: C += acc (raw accumulate)
// split-bf16: A*W ~= Ahi*Whi + Ahi*Wlo + Alo*Whi, fp32 accumulate
struct GSrc {
    const float* A;
    const __nv_bfloat16* whi;       // tile-image blobs, 32KB each
    const __nv_bfloat16* wlo;
};

#define SM_AHI 0
#define SM_ALO 16384
#define SM_WHI 32768
#define SM_WLO 65536
#define SM_TOTAL 98304

template <int NS, int MODE>
__global__ void __launch_bounds__(256) gemm_mma(GSrc s0, GSrc s1, GSrc s2,
                                                const float* __restrict__ bias,
                                                float alpha, float* __restrict__ C, int M,
                                                const float* __restrict__ pinit,
                                                const float* __restrict__ linW,
                                                const float* __restrict__ linb,
                                                float* __restrict__ hout) {
    extern __shared__ __align__(128) char smem[];
    uint32_t sbase = smem_u32(smem);
    const int tid = threadIdx.x;
    const int wid = tid >> 5;
    const int lane = tid & 31;
    const int warp_m = wid & 1;    // 2 x 32 rows
    const int warp_n = wid >> 1;   // 4 x 32 cols
    const int m0 = blockIdx.x * 64;
    GSrc srcs[3] = {s0, s1, s2};

    float acc[2][4][4];
#pragma unroll
    for (int i = 0; i < 2; i++)
#pragma unroll
        for (int j = 0; j < 4; j++)
#pragma unroll
            for (int k = 0; k < 4; k++) acc[i][j][k] = 0.0f;

    const int a_row = warp_m * 32 + (lane & 15);
    const int a_cbase = (lane >> 4);
    const int w_row = warp_n * 32 + (lane & 7) + ((lane >> 4) << 3);
    const int w_cbase = (lane >> 3) & 1;
    const int l7 = lane & 7;

#pragma unroll
    for (int si = 0; si < NS; si++) {
        __syncthreads();
        {
            const uint4* wh = (const uint4*)srcs[si].whi;
            const uint4* wl = (const uint4*)srcs[si].wlo;
            uint4* dh = (uint4*)(smem + SM_WHI);
            uint4* dl = (uint4*)(smem + SM_WLO);
#pragma unroll
            for (int i = tid; i < 2048; i += 256) { dh[i] = wh[i]; dl[i] = wl[i]; }
        }
        {
            const float* A = srcs[si].A;
#pragma unroll
            for (int ci = tid; ci < 1024; ci += 256) {
                int row = ci >> 4, ch = ci & 15;
                int m = m0 + row;
                float4 v0 = make_float4(0.f, 0.f, 0.f, 0.f), v1 = v0;
                if (m < M) {
                    const float4* g = (const float4*)(A + (size_t)m * F + ch * 8);
                    v0 = g[0]; v1 = g[1];
                }
                float vals[8] = {v0.x, v0.y, v0.z, v0.w, v1.x, v1.y, v1.z, v1.w};
                uint32_t hi[4], lo[4];
#pragma unroll
                for (int j = 0; j < 4; j++) {
                    __nv_bfloat16 h0 = __float2bfloat16_rn(vals[2 * j]);
                    __nv_bfloat16 h1 = __float2bfloat16_rn(vals[2 * j + 1]);
                    __nv_bfloat16 l0 = __float2bfloat16_rn(vals[2 * j] - __bfloat162float(h0));
                    __nv_bfloat16 l1 = __float2bfloat16_rn(vals[2 * j + 1] - __bfloat162float(h1));
                    hi[j] = ((uint32_t)__bfloat16_as_ushort(h1) << 16) | __bfloat16_as_ushort(h0);
                    lo[j] = ((uint32_t)__bfloat16_as_ushort(l1) << 16) | __bfloat16_as_ushort(l0);
                }
                uint32_t o = tile_off(row, ch);
                *(uint4*)(smem + SM_AHI + o) = make_uint4(hi[0], hi[1], hi[2], hi[3]);
                *(uint4*)(smem + SM_ALO + o) = make_uint4(lo[0], lo[1], lo[2], lo[3]);
            }
        }
        __syncthreads();

#pragma unroll
        for (int ks = 0; ks < 8; ks++) {
            uint32_t whi[4][2], wlo[4][2];
#pragma unroll
            for (int p = 0; p < 2; p++) {
                uint32_t woff = (uint32_t)(w_row + p * 16) * 256 +
                                (uint32_t)(((ks * 2 + w_cbase) ^ l7) << 4);
                uint32_t r[4];
                ldm_x4(r, sbase + SM_WHI + woff);
                whi[p * 2][0] = r[0]; whi[p * 2][1] = r[1];
                whi[p * 2 + 1][0] = r[2]; whi[p * 2 + 1][1] = r[3];
                ldm_x4(r, sbase + SM_WLO + woff);
                wlo[p * 2][0] = r[0]; wlo[p * 2][1] = r[1];
                wlo[p * 2 + 1][0] = r[2]; wlo[p * 2 + 1][1] = r[3];
            }
#pragma unroll
            for (int mi = 0; mi < 2; mi++) {
                uint32_t aoff = (uint32_t)(a_row + mi * 16) * 256 +
                                (uint32_t)(((ks * 2 + a_cbase) ^ l7) << 4);
                uint32_t ah[4], al[4];
                ldm_x4(ah, sbase + SM_AHI + aoff);
                ldm_x4(al, sbase + SM_ALO + aoff);
#pragma unroll
                for (int ni = 0; ni < 4; ni++) {
                    mma_bf16(acc[mi][ni], ah, whi[ni]);
                    mma_bf16(acc[mi][ni], ah, wlo[ni]);
                    mma_bf16(acc[mi][ni], al, whi[ni]);
                }
            }
        }
    }

    if (MODE != 2) {
#pragma unroll
        for (int mi = 0; mi < 2; mi++) {
            int m = m0 + warp_m * 32 + mi * 16 + (lane >> 2);
#pragma unroll
            for (int ni = 0; ni < 4; ni++) {
                int n = warp_n * 32 + ni * 8 + (lane & 3) * 2;
                float b0 = (MODE == 0) ? __ldg(&bias[n]) : 0.f;
                float b1 = (MODE == 0) ? __ldg(&bias[n + 1]) : 0.f;
                if (m < M) {
                    float2 o;
                    if (MODE == 0) {
                        o.x = fmaxf(fmaf(alpha, acc[mi][ni][0], b0), 0.f);
                        o.y = fmaxf(fmaf(alpha, acc[mi][ni][1], b1), 0.f);
                    } else if (MODE == 1) {
                        o.x = acc[mi][ni][0]; o.y = acc[mi][ni][1];
                    } else {  // MODE 3: accumulate
                        float2 c0 = *(float2*)(C + (size_t)m * F + n);
                        o.x = c0.x + acc[mi][ni][0]; o.y = c0.y + acc[mi][ni][1];
                    }
                    *(float2*)(C + (size_t)m * F + n) = o;
                }
                if (m + 8 < M) {
                    float2 o;
                    if (MODE == 0) {
                        o.x = fmaxf(fmaf(alpha, acc[mi][ni][2], b0), 0.f);
                        o.y = fmaxf(fmaf(alpha, acc[mi][ni][3], b1), 0.f);
                    } else if (MODE == 1) {
                        o.x = acc[mi][ni][2]; o.y = acc[mi][ni][3];
                    } else {
                        float2 c0 = *(float2*)(C + (size_t)(m + 8) * F + n);
                        o.x = c0.x + acc[mi][ni][2]; o.y = c0.y + acc[mi][ni][3];
                    }
                    *(float2*)(C + (size_t)(m + 8) * F + n) = o;
                }
            }
        }
    } else {
        // MODE 2: init-add + relu + fused head
        __syncthreads();
        float* slw = (float*)(smem + SM_WHI);     // reuse: 8x128 linW
        float* shred = (float*)(smem + SM_WLO);   // reuse: [row64][warp_n4][c8]
        for (int i = tid; i < 8 * F; i += 256) slw[i] = linW[i];
        __syncthreads();

        float hp[2][2][8];
#pragma unroll
        for (int a = 0; a < 2; a++)
#pragma unroll
            for (int b = 0; b < 2; b++)
#pragma unroll
                for (int c = 0; c < 8; c++) hp[a][b][c] = 0.f;

#pragma unroll
        for (int mi = 0; mi < 2; mi++) {
            int m = m0 + warp_m * 32 + mi * 16 + (lane >> 2);
#pragma unroll
            for (int ni = 0; ni < 4; ni++) {
                int n = warp_n * 32 + ni * 8 + (lane & 3) * 2;
                float2 pa = make_float2(0.f, 0.f), pb = make_float2(0.f, 0.f);
                if (m < M) pa = *(const float2*)(pinit + (size_t)m * F + n);
                if (m + 8 < M) pb = *(const float2*)(pinit + (size_t)(m + 8) * F + n);
                float b0 = __ldg(&bias[n]);
                float b1 = __ldg(&bias[n + 1]);
                float o0 = fmaxf(fmaf(alpha, acc[mi][ni][0] + pa.x, b0), 0.f);
                float o1 = fmaxf(fmaf(alpha, acc[mi][ni][1] + pa.y, b1), 0.f);
                float o2 = fmaxf(fmaf(alpha, acc[mi][ni][2] + pb.x, b0), 0.f);
                float o3 = fmaxf(fmaf(alpha, acc[mi][ni][3] + pb.y, b1), 0.f);
#pragma unroll
                for (int c = 0; c < 8; c++) {
                    float w0 = slw[c * F + n];
                    float w1 = slw[c * F + n + 1];
                    hp[mi][0][c] = fmaf(o0, w0, fmaf(o1, w1, hp[mi][0][c]));
                    hp[mi][1][c] = fmaf(o2, w0, fmaf(o3, w1, hp[mi][1][c]));
                }
            }
        }
#pragma unroll
        for (int a = 0; a < 2; a++)
#pragma unroll
            for (int b = 0; b < 2; b++)
#pragma unroll
                for (int c = 0; c < 8; c++) {
                    float v = hp[a][b][c];
                    v += __shfl_xor_sync(0xFFFFFFFF, v, 1);
                    v += __shfl_xor_sync(0xFFFFFFFF, v, 2);
                    hp[a][b][c] = v;
                }
        if ((lane & 3) == 0) {
#pragma unroll
            for (int mi = 0; mi < 2; mi++)
#pragma unroll
                for (int h = 0; h < 2; h++) {
                    int rl = warp_m * 32 + mi * 16 + (lane >> 2) + h * 8;
#pragma unroll
                    for (int c = 0; c < 8; c++)
                        shred[rl * 32 + warp_n * 8 + c] = hp[mi][h][c];
                }
        }
        __syncthreads();
#pragma unroll
        for (int idx = tid; idx < 512; idx += 256) {
            int row = idx >> 3, c = idx & 7;
            int m = m0 + row;
            if (m < M) {
                float s = shred[row * 32 + c] + shred[row * 32 + 8 + c] +
                          shred[row * 32 + 16 + c] + shred[row * 32 + 24 + c] + __ldg(&linb[c]);
                hout[(size_t)m * 8 + c] = s;
            }
        }
    }
}

// ============================ launch ============================
extern "C" void kernel_launch(void* const* d_in, const int* in_sizes, int n_in,
                              void* d_out, int out_size) {
    const float* x_p    = (const float*)d_in[0];
    const float* x_a    = (const float*)d_in[1];
    const int*   c_src  = (const int*)d_in[2];
    const int*   c_dst  = (const int*)d_in[3];
    const int*   ao_src = (const int*)d_in[4];
    const int*   ao_dst = (const int*)d_in[5];
    const int*   ha_src = (const int*)d_in[6];
    const int*   ha_dst = (const int*)d_in[7];
    const float* l1c_Wl = (const float*)d_in[8];
    const float* l1c_bl = (const float*)d_in[9];
    const float* l1c_Wr = (const float*)d_in[10];
    const float* l1a_Wl = (const float*)d_in[11];
    const float* l1a_bl = (const float*)d_in[12];
    const float* l1a_Wr = (const float*)d_in[13];
    const float* l1h_Wl = (const float*)d_in[14];
    const float* l1h_bl = (const float*)d_in[15];
    const float* l1h_Wr = (const float*)d_in[16];
    const float* l2c_Wl = (const float*)d_in[17];
    const float* l2c_bl = (const float*)d_in[18];
    const float* l2c_Wr = (const float*)d_in[19];
    const float* l2a_Wl = (const float*)d_in[20];
    const float* l2a_bl = (const float*)d_in[21];
    const float* l2a_Wr = (const float*)d_in[22];
    const float* lin_W  = (const float*)d_in[26];
    const float* lin_b  = (const float*)d_in[27];
    float* out = (float*)d_out;

    const int NP = in_sizes[0] / F;
    const int NA = in_sizes[1] / F;
    const int E  = in_sizes[2];
    const int n3 = 2 * NP + NA;

    float *agg_c, *agg_a, *agg_h, *agg_c2, *agg_a2, *p1, *a1, *pbuf, *b1, *b2;
    int *cnt3, *rp3, *col3, *part;
    __nv_bfloat16* wblob;
    cudaGetSymbolAddress((void**)&agg_c, g_agg_c);
    cudaGetSymbolAddress((void**)&agg_a, g_agg_a);
    cudaGetSymbolAddress((void**)&agg_h, g_agg_h);
    cudaGetSymbolAddress((void**)&agg_c2, g_agg_c2);
    cudaGetSymbolAddress((void**)&agg_a2, g_agg_a2);
    cudaGetSymbolAddress((void**)&p1, g_p1);
    cudaGetSymbolAddress((void**)&a1, g_a1);
    cudaGetSymbolAddress((void**)&pbuf, g_pbuf);
    cudaGetSymbolAddress((void**)&b1, g_b1);
    cudaGetSymbolAddress((void**)&b2, g_b2);
    cudaGetSymbolAddress((void**)&wblob, g_wblob);
    cudaGetSymbolAddress((void**)&cnt3, g_cnt3);
    cudaGetSymbolAddress((void**)&rp3, g_rp3);
    cudaGetSymbolAddress((void**)&col3, g_col3);
    cudaGetSymbolAddress((void**)&part, g_part);

    cudaFuncSetAttribute(gemm_mma<3, 0>, cudaFuncAttributeMaxDynamicSharedMemorySize, SM_TOTAL);
    cudaFuncSetAttribute(gemm_mma<2, 0>, cudaFuncAttributeMaxDynamicSharedMemorySize, SM_TOTAL);
    cudaFuncSetAttribute(gemm_mma<1, 1>, cudaFuncAttributeMaxDynamicSharedMemorySize, SM_TOTAL);
    cudaFuncSetAttribute(gemm_mma<1, 3>, cudaFuncAttributeMaxDynamicSharedMemorySize, SM_TOTAL);
    cudaFuncSetAttribute(gemm_mma<1, 2>, cudaFuncAttributeMaxDynamicSharedMemorySize, SM_TOTAL);

    const int tb = 256;
    const int eb3 = (3 * E + tb - 1) / tb;
    const int nb3 = (n3 + 2047) / 2048;
    const int gb_p = (NP * 32 + tb - 1) / tb;
    const int gb_a = (NA * 32 + tb - 1) / tb;

    auto WB = [&](int m, int half) -> const __nv_bfloat16* {
        return wblob + ((size_t)m * 2 + half) * F * F;
    };

    // ---- second stream + fork/join events (host objects; no device mem) ----
    cudaStream_t s1;
    cudaStreamCreateWithFlags(&s1, cudaStreamNonBlocking);
    cudaEvent_t evRoot, evPrep, evCSR, evP1, evS1;
    cudaEventCreateWithFlags(&evRoot, cudaEventDisableTiming);
    cudaEventCreateWithFlags(&evPrep, cudaEventDisableTiming);
    cudaEventCreateWithFlags(&evCSR, cudaEventDisableTiming);
    cudaEventCreateWithFlags(&evP1, cudaEventDisableTiming);
    cudaEventCreateWithFlags(&evS1, cudaEventDisableTiming);

    cudaEventRecord(evRoot, 0);
    cudaStreamWaitEvent(s1, evRoot, 0);

    // ---- s1: weight prep ----
    prep_bias_kernel<<<1, 128, 0, s1>>>(l1c_bl, l1a_bl, l2c_bl, l2a_bl);
    W8 w8;
    w8.a[0] = l1c_Wl; w8.b[0] = nullptr;
    w8.a[1] = l1a_Wl; w8.b[1] = nullptr;
    w8.a[2] = l1c_Wr; w8.b[2] = l1a_Wr;    // Wr1 = sum
    w8.a[3] = l1h_Wl; w8.b[3] = nullptr;
    w8.a[4] = l1h_Wr; w8.b[4] = nullptr;
    w8.a[5] = l2c_Wl; w8.b[5] = nullptr;
    w8.a[6] = l2a_Wl; w8.b[6] = nullptr;
    w8.a[7] = l2c_Wr; w8.b[7] = l2a_Wr;    // Wr2 = sum
    prep_w_kernel<<<dim3(8, 8), 256, 0, s1>>>(w8);
    cudaEventRecord(evPrep, s1);

    // ---- s0: fused CSR build ----
    cudaMemsetAsync(cnt3, 0, (size_t)n3 * sizeof(int), 0);
    count3_kernel<<<eb3, tb>>>(c_dst, ao_dst, ha_dst, cnt3, E, NP);
    scanA_kernel<<<nb3, 1024>>>(cnt3, part, n3);
    scanB_kernel<<<1, 128>>>(part, rp3 + n3, nb3);
    scanC_kernel<<<nb3, 1024>>>(cnt3, part, rp3, n3);
    fill3_kernel<<<eb3, tb>>>(c_src, c_dst, ao_src, ao_dst, ha_src, ha_dst,
                              rp3, cnt3, col3, E, NP);
    cudaEventRecord(evCSR, 0);
    cudaStreamWaitEvent(s1, evCSR, 0);

    // ---- s1: author chain, then partials of the final GEMM ----
    gather_kernel<<<gb_a, tb, 0, s1>>>(x_p, rp3 + 2 * NP, col3, agg_h, NA);
    {
        GSrc sh{agg_h, WB(3, 0), WB(3, 1)};
        GSrc sxa{x_a, WB(4, 0), WB(4, 1)};
        gemm_mma<2, 0><<<(NA + 63) / 64, 256, SM_TOTAL, s1>>>(
            sh, sxa, sxa, l1h_bl, 1.0f, a1, NA, nullptr, nullptr, nullptr, nullptr);
    }
    gather_kernel<<<gb_p, tb, 0, s1>>>(a1, rp3 + NP, col3, agg_a2, NP);
    {   // pbuf = agg_a2 @ l2a_Wl  (no dependence on p1 — starts immediately)
        GSrc sa2{agg_a2, WB(6, 0), WB(6, 1)};
        gemm_mma<1, 1><<<(NP + 63) / 64, 256, SM_TOTAL, s1>>>(
            sa2, sa2, sa2, nullptr, 1.0f, pbuf, NP, nullptr, nullptr, nullptr, nullptr);
    }
    cudaStreamWaitEvent(s1, evP1, 0);
    {   // pbuf += p1 @ Wr2
        GSrc sp{p1, WB(7, 0), WB(7, 1)};
        gemm_mma<1, 3><<<(NP + 63) / 64, 256, SM_TOTAL, s1>>>(
            sp, sp, sp, nullptr, 1.0f, pbuf, NP, nullptr, nullptr, nullptr, nullptr);
    }
    cudaEventRecord(evS1, s1);

    // ---- s0: patent chain ----
    gather_kernel<<<gb_p, tb>>>(x_p, rp3, col3, agg_c, NP);
    gather_kernel<<<gb_p, tb>>>(x_a, rp3 + NP, col3, agg_a, NP);
    cudaStreamWaitEvent(0, evPrep, 0);
    {
        GSrc sc{agg_c, WB(0, 0), WB(0, 1)};
        GSrc sa{agg_a, WB(1, 0), WB(1, 1)};
        GSrc sx{x_p, WB(2, 0), WB(2, 1)};
        gemm_mma<3, 0><<<(NP + 63) / 64, 256, SM_TOTAL>>>(
            sc, sa, sx, b1, 0.5f, p1, NP, nullptr, nullptr, nullptr, nullptr);
    }
    cudaEventRecord(evP1, 0);
    gather_kernel<<<gb_p, tb>>>(p1, rp3, col3, agg_c2, NP);

    // ---- join: final NS=1 GEMM with init (pbuf) + fused head ----
    cudaStreamWaitEvent(0, evS1, 0);
    {
        GSrc sc2{agg_c2, WB(5, 0), WB(5, 1)};
        gemm_mma<1, 2><<<(NP + 63) / 64, 256, SM_TOTAL>>>(
            sc2, sc2, sc2, b2, 0.5f, nullptr, NP, pbuf, lin_W, lin_b, out);
    }
}